// round 17
// baseline (speedup 1.0000x reference)
#include <cuda_runtime.h>

// Problem constants
#define N_TOTAL 2048
#define B_TOTAL 64
#define ED 512
#define SPLITS 16
#define ROWS_PER_CTA (N_TOTAL / SPLITS)  // 128
#define WARPS 4
#define THREADS (WARPS * 32)             // 128

// Per-batch global accumulators. Zero-init at load; the divide kernel resets
// them to zero after reading, so every graph replay starts from zeros.
__device__ __align__(16) float g_acc[B_TOTAL * ED];   // 128 KB, stays L2-hot
__device__ float g_s[B_TOTAL];

// ---------------------------------------------------------------------------
// Row processing: dot(v, w_smem) -> warp logit -> exp -> weighted accumulate.
// W_e lives in SMEM (identical for all warps) so registers go to the second
// row buffer instead; ptxas rematerializes the LDS under the 64-reg cap.
// ---------------------------------------------------------------------------
__device__ __forceinline__ void process_row(
    const float4 v[4], const float* __restrict__ sm_w, int lane,
    float& s, float4 acc[4])
{
    float d0 = 0.f, d1 = 0.f, d2 = 0.f, d3 = 0.f;
    {
        const float4 w0 = *reinterpret_cast<const float4*>(&sm_w[0 * 128 + lane * 4]);
        d0 = fmaf(v[0].x, w0.x, d0); d0 = fmaf(v[0].y, w0.y, d0);
        d0 = fmaf(v[0].z, w0.z, d0); d0 = fmaf(v[0].w, w0.w, d0);
    }
    {
        const float4 w1 = *reinterpret_cast<const float4*>(&sm_w[1 * 128 + lane * 4]);
        d1 = fmaf(v[1].x, w1.x, d1); d1 = fmaf(v[1].y, w1.y, d1);
        d1 = fmaf(v[1].z, w1.z, d1); d1 = fmaf(v[1].w, w1.w, d1);
    }
    {
        const float4 w2 = *reinterpret_cast<const float4*>(&sm_w[2 * 128 + lane * 4]);
        d2 = fmaf(v[2].x, w2.x, d2); d2 = fmaf(v[2].y, w2.y, d2);
        d2 = fmaf(v[2].z, w2.z, d2); d2 = fmaf(v[2].w, w2.w, d2);
    }
    {
        const float4 w3 = *reinterpret_cast<const float4*>(&sm_w[3 * 128 + lane * 4]);
        d3 = fmaf(v[3].x, w3.x, d3); d3 = fmaf(v[3].y, w3.y, d3);
        d3 = fmaf(v[3].z, w3.z, d3); d3 = fmaf(v[3].w, w3.w, d3);
    }
    float d = (d0 + d1) + (d2 + d3);
#pragma unroll
    for (int o = 16; o > 0; o >>= 1) d += __shfl_xor_sync(0xffffffffu, d, o);

    const float p = __expf(d);   // logits O(1); no max subtraction needed
    s += p;
#pragma unroll
    for (int q = 0; q < 4; q++) {
        acc[q].x = fmaf(p, v[q].x, acc[q].x);
        acc[q].y = fmaf(p, v[q].y, acc[q].y);
        acc[q].z = fmaf(p, v[q].z, acc[q].z);
        acc[q].w = fmaf(p, v[q].w, acc[q].w);
    }
}

// ---------------------------------------------------------------------------
// Kernel A: one-pass fused logits + softmax-numerator + weighted accumulate.
//  - softmax(x+c)==softmax(x) -> state_tm1/W_s/b cancel, never read.
//  - 1024 CTAs x 128 threads @ 8/SM: single wave, ~1.2% imbalance.
//  - DOUBLE-BUFFERED row loads: next row's 4x LDG.128 issue before current
//    row's compute chain -> ~32KB/SM in flight (was ~16KB; need ~28KB to
//    saturate DRAM). W_e moved to SMEM to pay for the second buffer.
//  - epilogue unchanged (R9): smem staging merge -> REDG.ADD, then PDL.
// ---------------------------------------------------------------------------
__global__ __launch_bounds__(THREADS, 8) void attn_main(
    const float* __restrict__ emb,   // (N, B, ED)
    const float* __restrict__ W)     // (SD+ED, 1); we use W[512..1023]
{
    const int b     = blockIdx.y;
    const int split = blockIdx.x;
    const int wid   = threadIdx.x >> 5;
    const int lane  = threadIdx.x & 31;

    __shared__ __align__(16) float sm_w[ED];             // W_e, shared by all warps
    __shared__ __align__(16) float sm_stage[WARPS][ED];  // 8 KB epilogue staging
    __shared__ float sm_s[WARPS];

    *reinterpret_cast<float4*>(&sm_w[threadIdx.x * 4]) =
        *reinterpret_cast<const float4*>(&W[512 + threadIdx.x * 4]);
    __syncthreads();

    float s = 0.0f;
    float4 acc[4];
#pragma unroll
    for (int q = 0; q < 4; q++) acc[q] = make_float4(0.f, 0.f, 0.f, 0.f);

    const int n0 = split * ROWS_PER_CTA;
    // This warp's rows: n0+wid, n0+wid+WARPS, ... (32 rows). float4 pointer.
    const float4* p = reinterpret_cast<const float4*>(
        emb + ((size_t)(n0 + wid) * B_TOTAL + b) * ED) + lane;
    const size_t rstride = (size_t)WARPS * B_TOTAL * (ED / 4);  // float4 units

    float4 va[4], vb[4];

    // prologue: row 0 (of this warp's 32)
#pragma unroll
    for (int q = 0; q < 4; q++) va[q] = __ldcs(&p[q * 32]);
    p += rstride;

    // steady state: 15 pair-iterations, loads always one row ahead
#pragma unroll 1
    for (int it = 0; it < 15; it++) {
#pragma unroll
        for (int q = 0; q < 4; q++) vb[q] = __ldcs(&p[q * 32]);   // row 2it+1
        p += rstride;
        process_row(va, sm_w, lane, s, acc);                       // row 2it
#pragma unroll
        for (int q = 0; q < 4; q++) va[q] = __ldcs(&p[q * 32]);   // row 2it+2
        p += rstride;
        process_row(vb, sm_w, lane, s, acc);                       // row 2it+1
    }
    // tail: rows 30, 31
#pragma unroll
    for (int q = 0; q < 4; q++) vb[q] = __ldcs(&p[q * 32]);       // row 31
    process_row(va, sm_w, lane, s, acc);                           // row 30
    process_row(vb, sm_w, lane, s, acc);                           // row 31

    // ---- CTA epilogue: per-warp staging merge, then RED to global ----
    if (lane == 0) sm_s[wid] = s;   // s is warp-uniform
#pragma unroll
    for (int q = 0; q < 4; q++)
        *reinterpret_cast<float4*>(&sm_stage[wid][q * 128 + lane * 4]) = acc[q];
    __syncthreads();

    const int e = threadIdx.x * 4;
    float4 a = *reinterpret_cast<const float4*>(&sm_stage[0][e]);
#pragma unroll
    for (int wj = 1; wj < WARPS; wj++) {
        const float4 t = *reinterpret_cast<const float4*>(&sm_stage[wj][e]);
        a.x += t.x; a.y += t.y; a.z += t.z; a.w += t.w;
    }

    float* dst = &g_acc[b * ED + e];
    atomicAdd(&dst[0], a.x);   // REDG.ADD (no return value used)
    atomicAdd(&dst[1], a.y);
    atomicAdd(&dst[2], a.z);
    atomicAdd(&dst[3], a.w);
    if (threadIdx.x == 0)
        atomicAdd(&g_s[b], sm_s[0] + sm_s[1] + sm_s[2] + sm_s[3]);

    // PDL: allow the dependent (divide) grid to begin launching now.
    asm volatile("griddepcontrol.launch_dependents;" ::: "memory");
}

// ---------------------------------------------------------------------------
// Kernel B: divide + reset. 128 CTAs x 64 threads, one float4 per thread;
// small CTAs slot into SM space freed during attn_main's drain (PDL).
// b is uniform per CTA (each CTA covers half a batch).
// ---------------------------------------------------------------------------
__global__ __launch_bounds__(64) void attn_divide(float* __restrict__ out)
{
    asm volatile("griddepcontrol.wait;" ::: "memory");

    const int b   = blockIdx.x >> 1;                       // 2 CTAs per batch
    const int e4  = (blockIdx.x & 1) * 64 + threadIdx.x;   // float4 idx in batch
    const int idx = b * (ED / 4) + e4;

    float4* accp = reinterpret_cast<float4*>(g_acc) + idx;
    const float4 a  = __ldcg(accp);
    const float  st = __ldcg(&g_s[b]);                     // CTA-uniform
    const float inv = 1.0f / st;

    float4 r;
    r.x = a.x * inv; r.y = a.y * inv; r.z = a.z * inv; r.w = a.w * inv;
    reinterpret_cast<float4*>(out)[idx] = r;

    *accp = make_float4(0.f, 0.f, 0.f, 0.f);               // reset for replay
    if (threadIdx.x == 0 && (blockIdx.x & 1) == 0) g_s[b] = 0.0f;
}

// ---------------------------------------------------------------------------
extern "C" void kernel_launch(void* const* d_in, const int* in_sizes, int n_in,
                              void* d_out, int out_size)
{
    // Locate inputs by size (robust to metadata ordering):
    //   embeddings: N*B*ED = 67108864 elements; W: 1024 elements
    const float* emb = nullptr;
    const float* W   = nullptr;
    for (int i = 0; i < n_in; i++) {
        if (in_sizes[i] == N_TOTAL * B_TOTAL * ED) emb = (const float*)d_in[i];
        else if (in_sizes[i] == 1024)              W   = (const float*)d_in[i];
    }

    dim3 grid(SPLITS, B_TOTAL);
    attn_main<<<grid, THREADS>>>(emb, W);

    // Dependent launch with Programmatic Stream Serialization (PDL).
    cudaLaunchConfig_t cfg = {};
    cfg.gridDim  = dim3(128);
    cfg.blockDim = dim3(64);
    cudaLaunchAttribute attrs[1];
    attrs[0].id = cudaLaunchAttributeProgrammaticStreamSerialization;
    attrs[0].val.programmaticStreamSerializationAllowed = 1;
    cfg.attrs = attrs;
    cfg.numAttrs = 1;
    cudaLaunchKernelEx(&cfg, attn_divide, (float*)d_out);
}